// round 8
// baseline (speedup 1.0000x reference)
#include <cuda_runtime.h>
#include <cuda_bf16.h>
#include <cstdint>

#define BTOT  16384
#define T     28
#define INP   28
#define H     64
#define MROWS 128
#define NT    256
#define OUTD  10

// ---- dynamic SMEM layout (byte offsets) ----
// A tiles (double-buffered): [rf 0..7][kf 0..5][lane 0..31][16B], hi then lo
#define ABUF     24576
#define OFF_A0HI 0
#define OFF_A0LO 24576
#define OFF_A1HI 49152
#define OFF_A1LO 73728
// B tiles: [w 0..7][kf 0..5][nf 0..3][lane 0..31][8B]
#define OFF_BHI  98304
#define OFF_BLO  147456
#define SMEM_BYTES 196608
// epilogue reuse (A regions dead after the loop): h_f32 at bytes 0..32768
#define OFF_WFC  36864
#define OFF_BFC  39424
#define OFF_PART 40960

__device__ __forceinline__ uint32_t smem_u32(const void* p) {
    uint32_t a;
    asm("{ .reg .u64 t; cvta.to.shared.u64 t, %1; cvt.u32.u64 %0, t; }" : "=r"(a) : "l"(p));
    return a;
}
__device__ __forceinline__ void sts32(uint32_t a, uint32_t v) {
    asm volatile("st.shared.b32 [%0], %1;" :: "r"(a), "r"(v) : "memory");
}
__device__ __forceinline__ void lds128(uint32_t* r, uint32_t a) {
    asm volatile("ld.shared.v4.b32 {%0,%1,%2,%3}, [%4];"
                 : "=r"(r[0]), "=r"(r[1]), "=r"(r[2]), "=r"(r[3]) : "r"(a));
}
__device__ __forceinline__ void lds64(uint32_t* r, uint32_t a) {
    asm volatile("ld.shared.v2.b32 {%0,%1}, [%2];" : "=r"(r[0]), "=r"(r[1]) : "r"(a));
}

// split two f32 into packed bf16x2 hi + bf16x2 residual lo
__device__ __forceinline__ void split2(float a, float b, uint32_t& hi, uint32_t& lo) {
    __nv_bfloat162 h2; h2.x = __float2bfloat16_rn(a); h2.y = __float2bfloat16_rn(b);
    __nv_bfloat162 l2;
    l2.x = __float2bfloat16_rn(a - __bfloat162float(h2.x));
    l2.y = __float2bfloat16_rn(b - __bfloat162float(h2.y));
    hi = *reinterpret_cast<uint32_t*>(&h2);
    lo = *reinterpret_cast<uint32_t*>(&l2);
}

__device__ __forceinline__ float tanha(float x) {
    float y; asm("tanh.approx.f32 %0, %1;" : "=f"(y) : "f"(x)); return y;
}
__device__ __forceinline__ float sigm(float x) { return fmaf(0.5f, tanha(0.5f * x), 0.5f); }

// m16n8k16 bf16 MMA, D += A*B (C aliased to D)
__device__ __forceinline__ void mma16816(float* d, const uint32_t* a, const uint32_t* b) {
    asm volatile(
        "mma.sync.aligned.m16n8k16.row.col.f32.bf16.bf16.f32 "
        "{%0,%1,%2,%3}, {%4,%5,%6,%7}, {%8,%9}, {%0,%1,%2,%3};"
        : "+f"(d[0]), "+f"(d[1]), "+f"(d[2]), "+f"(d[3])
        : "r"(a[0]), "r"(a[1]), "r"(a[2]), "r"(a[3]), "r"(b[0]), "r"(b[1]));
}

// weight element with K mapping: k 0..27 -> W_ih, 28..31 -> 0, 32..95 -> W_hh
__device__ __forceinline__ float wval(const float* __restrict__ Wih,
                                      const float* __restrict__ Whh, int g, int k) {
    if (k < INP)  return Wih[g * INP + k];
    if (k < 32)   return 0.0f;
    return Whh[g * H + (k - 32)];
}

__global__ void __launch_bounds__(NT, 1) lstm_mma_kernel(
    const float* __restrict__ x,    const float* __restrict__ W_ih,
    const float* __restrict__ W_hh, const float* __restrict__ b_ih,
    const float* __restrict__ b_hh, const float* __restrict__ W_fc,
    const float* __restrict__ b_fc, float* __restrict__ out)
{
    extern __shared__ char sm[];
    const uint32_t sb  = smem_u32(sm);
    const int tid  = threadIdx.x;
    const int w    = tid >> 5;          // warp: owns gate-cols for units w*8..w*8+7
    const int lane = tid & 31;
    const int g8   = lane >> 2;         // groupID
    const int tig  = lane & 3;          // threadID in group
    const int b0   = blockIdx.x * MROWS;

    // ---- zero BOTH A buffers (covers x-pad k28..31 and h0 = 0) ----
    {
        uint4* az = reinterpret_cast<uint4*>(sm);
        uint4 z = make_uint4(0u, 0u, 0u, 0u);
        for (int i = tid; i < OFF_BHI / 16; i += NT) az[i] = z;
    }

    // ---- build B fragments (hi/lo), fragment-major ----
    for (int ii = tid; ii < 8 * 6 * 4 * 32 * 2; ii += NT) {
        int reg = ii & 1;
        int t_  = (ii >> 1) & 31;
        int nf  = (ii >> 6) & 3;
        int kfn = (ii >> 8);
        int kf  = kfn % 6;
        int w_  = kfn / 6;
        int k0  = kf * 16 + reg * 8 + 2 * (t_ & 3);
        int g   = nf * 64 + w_ * 8 + (t_ >> 2);
        float v0 = wval(W_ih, W_hh, g, k0);
        float v1 = wval(W_ih, W_hh, g, k0 + 1);
        uint32_t hi, lo; split2(v0, v1, hi, lo);
        uint32_t boff = (uint32_t)(((w_ * 6 + kf) * 4 + nf) * 256 + t_ * 8 + reg * 4);
        sts32(sb + OFF_BHI + boff, hi);
        sts32(sb + OFF_BLO + boff, lo);
    }

    // ---- per-thread bias ----
    float bias2[4][2];
#pragma unroll
    for (int nf = 0; nf < 4; nf++)
#pragma unroll
        for (int ul = 0; ul < 2; ul++) {
            int g = nf * 64 + w * 8 + 2 * tig + ul;
            bias2[nf][ul] = b_ih[g] + b_hh[g];
        }

    // ---- x staging map: 7 pairs/thread over [128 rows x 14 pairs] ----
    int      xgb[7];
    uint32_t xsa[7];     // byte offset inside an A tile (buffer-relative)
#pragma unroll
    for (int i = 0; i < 7; i++) {
        int p  = tid + i * NT;
        int r  = p / 14;
        int kp = (p % 14) * 2;
        xgb[i] = ((b0 + r) * T) * INP + kp;
        int rf = r >> 4, gp = r & 7, rh = (r >> 3) & 1;
        int kf = kp >> 4, ki = kp & 15;
        xsa[i] = (uint32_t)((rf * 6 + kf) * 512 + (gp * 4 + ((ki & 7) >> 1)) * 16
                            + (ki >> 3) * 8 + rh * 4);
    }

    __syncthreads();   // zeroing complete before x(0) staging

    // ---- stage x(0) into buffer 0 ----
#pragma unroll
    for (int i = 0; i < 7; i++) {
        float2 v = *reinterpret_cast<const float2*>(x + xgb[i]);
        uint32_t hi, lo; split2(v.x, v.y, hi, lo);
        sts32(sb + OFF_A0HI + xsa[i], hi);
        sts32(sb + OFF_A0LO + xsa[i], lo);
    }

    // ---- h writeback base (k0h = 32 + w*8 + 2*tig), buffer-relative ----
    const int k0h = 32 + w * 8 + 2 * tig;
    const uint32_t hbase = (uint32_t)(((k0h >> 4) * 32 + g8 * 4 + ((k0h & 7) >> 1)) * 16
                                      + ((k0h >> 3) & 1) * 8);

    float c[32];
#pragma unroll
    for (int i = 0; i < 32; i++) c[i] = 0.0f;

    // =========================== timestep loop ===============================
    for (int t = 0; t < T; t++) {
        __syncthreads();   // buf(t&1) fully staged (h + x from t-1)

        const uint32_t aHI = sb + ((t & 1) ? OFF_A1HI : OFF_A0HI);
        const uint32_t aLO = aHI + ABUF;
        const uint32_t nHI = sb + ((t & 1) ? OFF_A0HI : OFF_A1HI);
        const uint32_t nLO = nHI + ABUF;
        const bool last = (t == T - 1);

        // ---- prefetch x(t+1) early (consumed at end of iteration) ----
        float2 xp[7];
        if (!last) {
#pragma unroll
            for (int i = 0; i < 7; i++)
                xp[i] = *reinterpret_cast<const float2*>(x + xgb[i] + (t + 1) * INP);
        }

        // ---- two row-groups: MMA then eltwise per group (in-warp pipeline,
        //      cross-warp the phases slide -> tensor/MUFU overlap) ----
#pragma unroll
        for (int grp = 0; grp < 2; grp++) {
            float d[4][4][4];
#pragma unroll
            for (int rf4 = 0; rf4 < 4; rf4++)
#pragma unroll
                for (int nf = 0; nf < 4; nf++)
#pragma unroll
                    for (int sl = 0; sl < 4; sl++)
                        d[rf4][nf][sl] = bias2[nf][sl & 1];

#pragma unroll
            for (int kf = 0; kf < 6; kf++) {
                uint32_t bh[4][2], bl[4][2];
#pragma unroll
                for (int nf = 0; nf < 4; nf++) {
                    uint32_t boff = (uint32_t)(((w * 6 + kf) * 4 + nf) * 256 + lane * 8);
                    lds64(bh[nf], sb + OFF_BHI + boff);
                    lds64(bl[nf], sb + OFF_BLO + boff);
                }
#pragma unroll
                for (int rf4 = 0; rf4 < 4; rf4++) {
                    const int rf = grp * 4 + rf4;
                    uint32_t aoff = (uint32_t)((rf * 6 + kf) * 512 + lane * 16);
                    uint32_t ah[4], al[4];
                    lds128(ah, aHI + aoff);
                    lds128(al, aLO + aoff);
#pragma unroll
                    for (int nf = 0; nf < 4; nf++) {
                        mma16816(d[rf4][nf], ah, bh[nf]);
                        mma16816(d[rf4][nf], al, bh[nf]);
                        mma16816(d[rf4][nf], ah, bl[nf]);
                    }
                }
            }

            // ---- eltwise for this group (register-local gates) ----
#pragma unroll
            for (int rf4 = 0; rf4 < 4; rf4++) {
                const int rf = grp * 4 + rf4;
#pragma unroll
                for (int rh = 0; rh < 2; rh++) {
                    float hv[2];
#pragma unroll
                    for (int ul = 0; ul < 2; ul++) {
                        int sl = 2 * rh + ul;
                        int ci = rf * 4 + sl;
                        float gi = sigm(d[rf4][0][sl]);
                        float gf = sigm(d[rf4][1][sl]);
                        float gg = tanha(d[rf4][2][sl]);
                        float go = sigm(d[rf4][3][sl]);
                        float cm = fmaf(gf, c[ci], gi * gg);
                        c[ci] = cm;
                        hv[ul] = go * tanha(cm);
                    }
                    if (!last) {
                        uint32_t hi, lo; split2(hv[0], hv[1], hi, lo);
                        uint32_t a = (uint32_t)(rf * 3072) + hbase + (uint32_t)(rh * 4);
                        sts32(nHI + a, hi);
                        sts32(nLO + a, lo);
                    } else {
                        // final step: dump f32 h_last into [r][j] at smem base
                        int r  = rf * 16 + g8 + 8 * rh;
                        int j0 = w * 8 + 2 * tig;
                        float* hf = reinterpret_cast<float*>(sm);
                        hf[r * H + j0]     = hv[0];
                        hf[r * H + j0 + 1] = hv[1];
                    }
                }
            }
        }

        // ---- commit x(t+1) into the next buffer ----
        if (!last) {
#pragma unroll
            for (int i = 0; i < 7; i++) {
                uint32_t hi, lo; split2(xp[i].x, xp[i].y, hi, lo);
                sts32(nHI + xsa[i], hi);
                sts32(nLO + xsa[i], lo);
            }
        }
    }

    // ======================= FC epilogue (fp32 SIMT) =========================
    __syncthreads();
    float* smf = reinterpret_cast<float*>(sm);
    for (int i = tid; i < OUTD * H; i += NT) smf[OFF_WFC / 4 + i] = W_fc[i];
    if (tid < OUTD) smf[OFF_BFC / 4 + tid] = b_fc[tid];
    __syncthreads();
    {
        const int half = tid >> 7, rr = tid & 127;
        float acc[OUTD];
#pragma unroll
        for (int o = 0; o < OUTD; o++) acc[o] = 0.0f;
#pragma unroll
        for (int p = 0; p < 32; p++) {
            int k = half * 32 + p;
            float hvv = smf[rr * H + k];
#pragma unroll
            for (int o = 0; o < OUTD; o++)
                acc[o] = fmaf(hvv, smf[OFF_WFC / 4 + o * H + k], acc[o]);
        }
#pragma unroll
        for (int o = 0; o < OUTD; o++)
            smf[OFF_PART / 4 + (half * 128 + rr) * OUTD + o] = acc[o];
    }
    __syncthreads();
    for (int i = tid; i < MROWS * OUTD; i += NT) {
        int rr = i / OUTD, o = i - rr * OUTD;
        out[(size_t)(b0 + rr) * OUTD + o] =
            smf[OFF_PART / 4 + rr * OUTD + o]
          + smf[OFF_PART / 4 + (128 + rr) * OUTD + o]
          + smf[OFF_BFC / 4 + o];
    }
}

extern "C" void kernel_launch(void* const* d_in, const int* in_sizes, int n_in,
                              void* d_out, int out_size) {
    const float* x    = (const float*)d_in[0];
    const float* W_ih = (const float*)d_in[1];
    const float* W_hh = (const float*)d_in[2];
    const float* b_ih = (const float*)d_in[3];
    const float* b_hh = (const float*)d_in[4];
    const float* W_fc = (const float*)d_in[5];
    const float* b_fc = (const float*)d_in[6];

    cudaFuncSetAttribute(lstm_mma_kernel,
                         cudaFuncAttributeMaxDynamicSharedMemorySize, SMEM_BYTES);
    lstm_mma_kernel<<<BTOT / MROWS, NT, SMEM_BYTES>>>(
        x, W_ih, W_hh, b_ih, b_hh, W_fc, b_fc, (float*)d_out);
}

// round 10
// speedup vs baseline: 2.1485x; 2.1485x over previous
#include <cuda_runtime.h>
#include <cuda_bf16.h>
#include <cstdint>

#define BTOT  16384
#define T     28
#define INP   28
#define H     64
#define MROWS 128
#define NT    256
#define OUTD  10

// ---- dynamic SMEM layout (byte offsets) ----
// A tiles hi-only, double-buffered: [rf 0..7][kf 0..5][lane 0..31][16B]
#define ABUF    24576
#define OFF_A0  0
#define OFF_A1  24576
// B tiles: [w 0..7][kf 0..5][nf 0..3][lane 0..31][8B], hi + lo
#define OFF_BHI 49152
#define OFF_BLO 98304
// dedicated f32 h_last dump (no overlap with live tiles on the last step)
#define OFF_HF  147456
#define SMEM_BYTES (147456 + 32768)
// epilogue reuse (A/B regions dead after the loop)
#define OFF_WFC  36864
#define OFF_BFC  39424
#define OFF_PART 40960

__device__ __forceinline__ uint32_t smem_u32(const void* p) {
    uint32_t a;
    asm("{ .reg .u64 t; cvta.to.shared.u64 t, %1; cvt.u32.u64 %0, t; }" : "=r"(a) : "l"(p));
    return a;
}
__device__ __forceinline__ void sts32(uint32_t a, uint32_t v) {
    asm volatile("st.shared.b32 [%0], %1;" :: "r"(a), "r"(v) : "memory");
}
__device__ __forceinline__ void lds128(uint32_t* r, uint32_t a) {
    asm volatile("ld.shared.v4.b32 {%0,%1,%2,%3}, [%4];"
                 : "=r"(r[0]), "=r"(r[1]), "=r"(r[2]), "=r"(r[3]) : "r"(a));
}
__device__ __forceinline__ void lds64(uint32_t* r, uint32_t a) {
    asm volatile("ld.shared.v2.b32 {%0,%1}, [%2];" : "=r"(r[0]), "=r"(r[1]) : "r"(a));
}

// pack two f32 into bf16x2 (round-to-nearest)
__device__ __forceinline__ uint32_t pack2(float a, float b) {
    __nv_bfloat162 h2; h2.x = __float2bfloat16_rn(a); h2.y = __float2bfloat16_rn(b);
    return *reinterpret_cast<uint32_t*>(&h2);
}
// split two f32 into bf16x2 hi + bf16x2 residual lo (weights only)
__device__ __forceinline__ void split2(float a, float b, uint32_t& hi, uint32_t& lo) {
    __nv_bfloat162 h2; h2.x = __float2bfloat16_rn(a); h2.y = __float2bfloat16_rn(b);
    __nv_bfloat162 l2;
    l2.x = __float2bfloat16_rn(a - __bfloat162float(h2.x));
    l2.y = __float2bfloat16_rn(b - __bfloat162float(h2.y));
    hi = *reinterpret_cast<uint32_t*>(&h2);
    lo = *reinterpret_cast<uint32_t*>(&l2);
}

__device__ __forceinline__ float tanha(float x) {
    float y; asm("tanh.approx.f32 %0, %1;" : "=f"(y) : "f"(x)); return y;
}
__device__ __forceinline__ float sigm(float x) { return fmaf(0.5f, tanha(0.5f * x), 0.5f); }

// m16n8k16 bf16 MMA, D += A*B (C aliased to D)
__device__ __forceinline__ void mma16816(float* d, const uint32_t* a, const uint32_t* b) {
    asm volatile(
        "mma.sync.aligned.m16n8k16.row.col.f32.bf16.bf16.f32 "
        "{%0,%1,%2,%3}, {%4,%5,%6,%7}, {%8,%9}, {%0,%1,%2,%3};"
        : "+f"(d[0]), "+f"(d[1]), "+f"(d[2]), "+f"(d[3])
        : "r"(a[0]), "r"(a[1]), "r"(a[2]), "r"(a[3]), "r"(b[0]), "r"(b[1]));
}

// weight element with K mapping: k 0..27 -> W_ih, 28..31 -> 0, 32..95 -> W_hh
__device__ __forceinline__ float wval(const float* __restrict__ Wih,
                                      const float* __restrict__ Whh, int g, int k) {
    if (k < INP)  return Wih[g * INP + k];
    if (k < 32)   return 0.0f;
    return Whh[g * H + (k - 32)];
}

__global__ void __launch_bounds__(NT, 1) lstm_mma_kernel(
    const float* __restrict__ x,    const float* __restrict__ W_ih,
    const float* __restrict__ W_hh, const float* __restrict__ b_ih,
    const float* __restrict__ b_hh, const float* __restrict__ W_fc,
    const float* __restrict__ b_fc, float* __restrict__ out)
{
    extern __shared__ char sm[];
    const uint32_t sb  = smem_u32(sm);
    const int tid  = threadIdx.x;
    const int w    = tid >> 5;          // warp: owns gate-cols for units w*8..w*8+7
    const int lane = tid & 31;
    const int g8   = lane >> 2;         // groupID
    const int tig  = lane & 3;          // threadID in group
    const int b0   = blockIdx.x * MROWS;

    // ---- zero both A buffers (covers x-pad k28..31 and h0 = 0) ----
    {
        uint4* az = reinterpret_cast<uint4*>(sm);
        uint4 z = make_uint4(0u, 0u, 0u, 0u);
        for (int i = tid; i < OFF_BHI / 16; i += NT) az[i] = z;
    }

    // ---- build B fragments (hi/lo), fragment-major ----
    for (int ii = tid; ii < 8 * 6 * 4 * 32 * 2; ii += NT) {
        int reg = ii & 1;
        int t_  = (ii >> 1) & 31;
        int nf  = (ii >> 6) & 3;
        int kfn = (ii >> 8);
        int kf  = kfn % 6;
        int w_  = kfn / 6;
        int k0  = kf * 16 + reg * 8 + 2 * (t_ & 3);
        int g   = nf * 64 + w_ * 8 + (t_ >> 2);
        float v0 = wval(W_ih, W_hh, g, k0);
        float v1 = wval(W_ih, W_hh, g, k0 + 1);
        uint32_t hi, lo; split2(v0, v1, hi, lo);
        uint32_t boff = (uint32_t)(((w_ * 6 + kf) * 4 + nf) * 256 + t_ * 8 + reg * 4);
        sts32(sb + OFF_BHI + boff, hi);
        sts32(sb + OFF_BLO + boff, lo);
    }

    // ---- per-thread bias ----
    float bias2[4][2];
#pragma unroll
    for (int nf = 0; nf < 4; nf++)
#pragma unroll
        for (int ul = 0; ul < 2; ul++) {
            int g = nf * 64 + w * 8 + 2 * tig + ul;
            bias2[nf][ul] = b_ih[g] + b_hh[g];
        }

    // ---- x staging map: 7 pairs/thread over [128 rows x 14 pairs] ----
    int      xgb[7];
    uint32_t xsa[7];     // byte offset inside an A tile (buffer-relative)
#pragma unroll
    for (int i = 0; i < 7; i++) {
        int p  = tid + i * NT;
        int r  = p / 14;
        int kp = (p % 14) * 2;
        xgb[i] = ((b0 + r) * T) * INP + kp;
        int rf = r >> 4, gp = r & 7, rh = (r >> 3) & 1;
        int kf = kp >> 4, ki = kp & 15;
        xsa[i] = (uint32_t)((rf * 6 + kf) * 512 + (gp * 4 + ((ki & 7) >> 1)) * 16
                            + (ki >> 3) * 8 + rh * 4);
    }

    __syncthreads();   // zeroing complete before x(0) staging

    // ---- stage x(0) into buffer 0 (hi only) ----
#pragma unroll
    for (int i = 0; i < 7; i++) {
        float2 v = *reinterpret_cast<const float2*>(x + xgb[i]);
        sts32(sb + OFF_A0 + xsa[i], pack2(v.x, v.y));
    }

    // ---- h writeback base (k0h = 32 + w*8 + 2*tig), buffer-relative ----
    const int k0h = 32 + w * 8 + 2 * tig;
    const uint32_t hbase = (uint32_t)(((k0h >> 4) * 32 + g8 * 4 + ((k0h & 7) >> 1)) * 16
                                      + ((k0h >> 3) & 1) * 8);

    float c[32];
#pragma unroll
    for (int i = 0; i < 32; i++) c[i] = 0.0f;

    // =========================== timestep loop ===============================
    for (int t = 0; t < T; t++) {
        __syncthreads();   // buf(t&1) fully staged (h + x from t-1)

        const uint32_t aCUR = sb + ((t & 1) ? OFF_A1 : OFF_A0);
        const uint32_t aNXT = sb + ((t & 1) ? OFF_A0 : OFF_A1);
        const bool last = (t == T - 1);

        // ---- D init = bias ----
        float d[8][4][4];
#pragma unroll
        for (int rf = 0; rf < 8; rf++)
#pragma unroll
            for (int nf = 0; nf < 4; nf++)
#pragma unroll
                for (int sl = 0; sl < 4; sl++)
                    d[rf][nf][sl] = bias2[nf][sl & 1];

        // ---- MMA phase: 2 terms (Ahi*Bhi + Ahi*Blo), monolithic 8-rf loop ----
#pragma unroll
        for (int kf = 0; kf < 6; kf++) {
            uint32_t bh[4][2], bl[4][2];
#pragma unroll
            for (int nf = 0; nf < 4; nf++) {
                uint32_t boff = (uint32_t)(((w * 6 + kf) * 4 + nf) * 256 + lane * 8);
                lds64(bh[nf], sb + OFF_BHI + boff);
                lds64(bl[nf], sb + OFF_BLO + boff);
            }
#pragma unroll
            for (int rf = 0; rf < 8; rf++) {
                uint32_t aoff = (uint32_t)((rf * 6 + kf) * 512 + lane * 16);
                uint32_t ah[4];
                lds128(ah, aCUR + aoff);
#pragma unroll
                for (int nf = 0; nf < 4; nf++) {
                    mma16816(d[rf][nf], ah, bh[nf]);
                    mma16816(d[rf][nf], ah, bl[nf]);
                }
            }
        }

        // ---- prefetch x(t+1) ----
        float2 xp[7];
        if (!last) {
#pragma unroll
            for (int i = 0; i < 7; i++)
                xp[i] = *reinterpret_cast<const float2*>(x + xgb[i] + (t + 1) * INP);
        }

        // ---- eltwise (register-local gates) + h writeback into next buffer ----
#pragma unroll
        for (int rf = 0; rf < 8; rf++) {
#pragma unroll
            for (int rh = 0; rh < 2; rh++) {
                float hv[2];
#pragma unroll
                for (int ul = 0; ul < 2; ul++) {
                    int sl = 2 * rh + ul;
                    int ci = rf * 4 + sl;
                    float gi = sigm(d[rf][0][sl]);
                    float gf = sigm(d[rf][1][sl]);
                    float gg = tanha(d[rf][2][sl]);
                    float go = sigm(d[rf][3][sl]);
                    float cm = fmaf(gf, c[ci], gi * gg);
                    c[ci] = cm;
                    hv[ul] = go * tanha(cm);
                }
                if (!last) {
                    uint32_t a = (uint32_t)(rf * 3072) + hbase + (uint32_t)(rh * 4);
                    sts32(aNXT + a, pack2(hv[0], hv[1]));
                } else {
                    // final step: dump f32 h_last into dedicated region [r][j]
                    int r  = rf * 16 + g8 + 8 * rh;
                    int j0 = w * 8 + 2 * tig;
                    float* hf = reinterpret_cast<float*>(sm + OFF_HF);
                    hf[r * H + j0]     = hv[0];
                    hf[r * H + j0 + 1] = hv[1];
                }
            }
        }

        // ---- commit x(t+1) into the next buffer (hi only) ----
        if (!last) {
#pragma unroll
            for (int i = 0; i < 7; i++)
                sts32(aNXT + xsa[i], pack2(xp[i].x, xp[i].y));
        }
    }

    // ======================= FC epilogue (fp32 SIMT) =========================
    __syncthreads();
    float* smf = reinterpret_cast<float*>(sm);
    const float* hf = reinterpret_cast<const float*>(sm + OFF_HF);
    for (int i = tid; i < OUTD * H; i += NT) smf[OFF_WFC / 4 + i] = W_fc[i];
    if (tid < OUTD) smf[OFF_BFC / 4 + tid] = b_fc[tid];
    __syncthreads();
    {
        const int half = tid >> 7, rr = tid & 127;
        float acc[OUTD];
#pragma unroll
        for (int o = 0; o < OUTD; o++) acc[o] = 0.0f;
#pragma unroll
        for (int p = 0; p < 32; p++) {
            int k = half * 32 + p;
            float hvv = hf[rr * H + k];
#pragma unroll
            for (int o = 0; o < OUTD; o++)
                acc[o] = fmaf(hvv, smf[OFF_WFC / 4 + o * H + k], acc[o]);
        }
#pragma unroll
        for (int o = 0; o < OUTD; o++)
            smf[OFF_PART / 4 + (half * 128 + rr) * OUTD + o] = acc[o];
    }
    __syncthreads();
    for (int i = tid; i < MROWS * OUTD; i += NT) {
        int rr = i / OUTD, o = i - rr * OUTD;
        out[(size_t)(b0 + rr) * OUTD + o] =
            smf[OFF_PART / 4 + rr * OUTD + o]
          + smf[OFF_PART / 4 + (128 + rr) * OUTD + o]
          + smf[OFF_BFC / 4 + o];
    }
}

extern "C" void kernel_launch(void* const* d_in, const int* in_sizes, int n_in,
                              void* d_out, int out_size) {
    const float* x    = (const float*)d_in[0];
    const float* W_ih = (const float*)d_in[1];
    const float* W_hh = (const float*)d_in[2];
    const float* b_ih = (const float*)d_in[3];
    const float* b_hh = (const float*)d_in[4];
    const float* W_fc = (const float*)d_in[5];
    const float* b_fc = (const float*)d_in[6];

    cudaFuncSetAttribute(lstm_mma_kernel,
                         cudaFuncAttributeMaxDynamicSharedMemorySize, SMEM_BYTES);
    lstm_mma_kernel<<<BTOT / MROWS, NT, SMEM_BYTES>>>(
        x, W_ih, W_hh, b_ih, b_hh, W_fc, b_fc, (float*)d_out);
}

// round 11
// speedup vs baseline: 2.9680x; 1.3815x over previous
#include <cuda_runtime.h>
#include <cuda_fp16.h>
#include <cstdint>

#define BTOT  16384
#define T     28
#define INP   28
#define H     64
#define MROWS 128
#define NT    512
#define OUTD  10

// ---- dynamic SMEM layout (byte offsets) ----
// A tiles fp16, double-buffered: [rf 0..7][kf 0..5][lane 0..31][16B]
#define ABUF    24576
#define OFF_A0  0
#define OFF_A1  24576
// B tile fp16 single-term: [w 0..7][kf 0..5][nf 0..3][lane 0..31][8B]
#define OFF_B   49152
// dedicated f32 h_last dump
#define OFF_HF  98304
#define SMEM_BYTES (98304 + 32768)
// epilogue reuse (A1/B dead after the loop)
#define OFF_WFC  36864
#define OFF_BFC  39424
#define OFF_PART 40960      // 4 * 128 * 10 f32 = 20480 B (ends 61440, inside dead B)

__device__ __forceinline__ uint32_t smem_u32(const void* p) {
    uint32_t a;
    asm("{ .reg .u64 t; cvta.to.shared.u64 t, %1; cvt.u32.u64 %0, t; }" : "=r"(a) : "l"(p));
    return a;
}
__device__ __forceinline__ void sts32(uint32_t a, uint32_t v) {
    asm volatile("st.shared.b32 [%0], %1;" :: "r"(a), "r"(v) : "memory");
}
__device__ __forceinline__ void lds128(uint32_t* r, uint32_t a) {
    asm volatile("ld.shared.v4.b32 {%0,%1,%2,%3}, [%4];"
                 : "=r"(r[0]), "=r"(r[1]), "=r"(r[2]), "=r"(r[3]) : "r"(a));
}
__device__ __forceinline__ void lds64(uint32_t* r, uint32_t a) {
    asm volatile("ld.shared.v2.b32 {%0,%1}, [%2];" : "=r"(r[0]), "=r"(r[1]) : "r"(a));
}

// pack two f32 into f16x2 (round-to-nearest)
__device__ __forceinline__ uint32_t pack2h(float a, float b) {
    __half2 h2; h2.x = __float2half_rn(a); h2.y = __float2half_rn(b);
    return *reinterpret_cast<uint32_t*>(&h2);
}

__device__ __forceinline__ float tanha(float x) {
    float y; asm("tanh.approx.f32 %0, %1;" : "=f"(y) : "f"(x)); return y;
}
__device__ __forceinline__ float sigm(float x) { return fmaf(0.5f, tanha(0.5f * x), 0.5f); }

// m16n8k16 fp16 MMA, D += A*B (C aliased to D), f32 accumulate
__device__ __forceinline__ void mma16816(float* d, const uint32_t* a, const uint32_t* b) {
    asm volatile(
        "mma.sync.aligned.m16n8k16.row.col.f32.f16.f16.f32 "
        "{%0,%1,%2,%3}, {%4,%5,%6,%7}, {%8,%9}, {%0,%1,%2,%3};"
        : "+f"(d[0]), "+f"(d[1]), "+f"(d[2]), "+f"(d[3])
        : "r"(a[0]), "r"(a[1]), "r"(a[2]), "r"(a[3]), "r"(b[0]), "r"(b[1]));
}

// weight element with K mapping: k 0..27 -> W_ih, 28..31 -> 0, 32..95 -> W_hh
__device__ __forceinline__ float wval(const float* __restrict__ Wih,
                                      const float* __restrict__ Whh, int g, int k) {
    if (k < INP)  return Wih[g * INP + k];
    if (k < 32)   return 0.0f;
    return Whh[g * H + (k - 32)];
}

__global__ void __launch_bounds__(NT, 1) lstm_mma_kernel(
    const float* __restrict__ x,    const float* __restrict__ W_ih,
    const float* __restrict__ W_hh, const float* __restrict__ b_ih,
    const float* __restrict__ b_hh, const float* __restrict__ W_fc,
    const float* __restrict__ b_fc, float* __restrict__ out)
{
    extern __shared__ char sm[];
    const uint32_t sb  = smem_u32(sm);
    const int tid  = threadIdx.x;
    const int w5   = tid >> 5;          // warp 0..15
    const int wn   = w5 & 7;            // unit-group: owns units wn*8..wn*8+7
    const int wm   = w5 >> 3;           // M-half: rf = wm*4 + rf4
    const int lane = tid & 31;
    const int g8   = lane >> 2;         // groupID
    const int tig  = lane & 3;          // threadID in group
    const int b0   = blockIdx.x * MROWS;

    // ---- zero both A buffers (covers x-pad k28..31 and h0 = 0) ----
    {
        uint4* az = reinterpret_cast<uint4*>(sm);
        uint4 z = make_uint4(0u, 0u, 0u, 0u);
        for (int i = tid; i < OFF_B / 16; i += NT) az[i] = z;
    }

    // ---- build B fragments (fp16 single-term), fragment-major ----
    for (int ii = tid; ii < 8 * 6 * 4 * 32 * 2; ii += NT) {
        int reg = ii & 1;
        int t_  = (ii >> 1) & 31;
        int nf  = (ii >> 6) & 3;
        int kfn = (ii >> 8);
        int kf  = kfn % 6;
        int w_  = kfn / 6;
        int k0  = kf * 16 + reg * 8 + 2 * (t_ & 3);
        int g   = nf * 64 + w_ * 8 + (t_ >> 2);
        float v0 = wval(W_ih, W_hh, g, k0);
        float v1 = wval(W_ih, W_hh, g, k0 + 1);
        uint32_t boff = (uint32_t)(((w_ * 6 + kf) * 4 + nf) * 256 + t_ * 8 + reg * 4);
        sts32(sb + OFF_B + boff, pack2h(v0, v1));
    }

    // ---- per-thread bias ----
    float bias2[4][2];
#pragma unroll
    for (int nf = 0; nf < 4; nf++)
#pragma unroll
        for (int ul = 0; ul < 2; ul++) {
            int g = nf * 64 + wn * 8 + 2 * tig + ul;
            bias2[nf][ul] = b_ih[g] + b_hh[g];
        }

    // ---- x staging map: up to 4 pairs/thread over [128 rows x 14 pairs] ----
    int      xgb[4];
    uint32_t xsa[4];
    const int nxp = (tid < 1792 - 3 * NT) ? 4 : 3;   // pairs this thread owns
#pragma unroll
    for (int i = 0; i < 4; i++) {
        int p  = tid + i * NT;
        if (p >= 1792) p = 0;           // dummy (masked by nxp)
        int r  = p / 14;
        int kp = (p % 14) * 2;
        xgb[i] = ((b0 + r) * T) * INP + kp;
        int rf = r >> 4, gp = r & 7, rh = (r >> 3) & 1;
        int kf = kp >> 4, ki = kp & 15;
        xsa[i] = (uint32_t)((rf * 6 + kf) * 512 + (gp * 4 + ((ki & 7) >> 1)) * 16
                            + (ki >> 3) * 8 + rh * 4);
    }

    __syncthreads();   // zeroing complete before x(0) staging

    // ---- stage x(0) into buffer 0 ----
#pragma unroll
    for (int i = 0; i < 4; i++) {
        if (i < nxp) {
            float2 v = *reinterpret_cast<const float2*>(x + xgb[i]);
            sts32(sb + OFF_A0 + xsa[i], pack2h(v.x, v.y));
        }
    }

    // ---- h writeback base (k0h = 32 + wn*8 + 2*tig), buffer-relative ----
    const int k0h = 32 + wn * 8 + 2 * tig;
    const uint32_t hbase = (uint32_t)(((k0h >> 4) * 32 + g8 * 4 + ((k0h & 7) >> 1)) * 16
                                      + ((k0h >> 3) & 1) * 8);

    float c[16];
#pragma unroll
    for (int i = 0; i < 16; i++) c[i] = 0.0f;

    // =========================== timestep loop ===============================
    for (int t = 0; t < T; t++) {
        __syncthreads();   // buf(t&1) fully staged (h + x from t-1)

        const uint32_t aCUR = sb + ((t & 1) ? OFF_A1 : OFF_A0);
        const uint32_t aNXT = sb + ((t & 1) ? OFF_A0 : OFF_A1);
        const bool last = (t == T - 1);

        // ---- D init = bias ----
        float d[4][4][4];
#pragma unroll
        for (int rf4 = 0; rf4 < 4; rf4++)
#pragma unroll
            for (int nf = 0; nf < 4; nf++)
#pragma unroll
                for (int sl = 0; sl < 4; sl++)
                    d[rf4][nf][sl] = bias2[nf][sl & 1];

        // ---- MMA phase: single term, 4 rf per warp ----
#pragma unroll
        for (int kf = 0; kf < 6; kf++) {
            uint32_t bh[4][2];
#pragma unroll
            for (int nf = 0; nf < 4; nf++) {
                uint32_t boff = (uint32_t)(((wn * 6 + kf) * 4 + nf) * 256 + lane * 8);
                lds64(bh[nf], sb + OFF_B + boff);
            }
#pragma unroll
            for (int rf4 = 0; rf4 < 4; rf4++) {
                const int rf = wm * 4 + rf4;
                uint32_t aoff = (uint32_t)((rf * 6 + kf) * 512 + lane * 16);
                uint32_t ah[4];
                lds128(ah, aCUR + aoff);
#pragma unroll
                for (int nf = 0; nf < 4; nf++)
                    mma16816(d[rf4][nf], ah, bh[nf]);
            }
        }

        // ---- prefetch x(t+1) ----
        float2 xp[4];
        if (!last) {
#pragma unroll
            for (int i = 0; i < 4; i++)
                if (i < nxp)
                    xp[i] = *reinterpret_cast<const float2*>(x + xgb[i] + (t + 1) * INP);
        }

        // ---- eltwise (register-local gates) + h writeback into next buffer ----
#pragma unroll
        for (int rf4 = 0; rf4 < 4; rf4++) {
            const int rf = wm * 4 + rf4;
#pragma unroll
            for (int rh = 0; rh < 2; rh++) {
                float hv[2];
#pragma unroll
                for (int ul = 0; ul < 2; ul++) {
                    int sl = 2 * rh + ul;
                    int ci = rf4 * 4 + sl;
                    float gi = sigm(d[rf4][0][sl]);
                    float gf = sigm(d[rf4][1][sl]);
                    float gg = tanha(d[rf4][2][sl]);
                    float go = sigm(d[rf4][3][sl]);
                    float cm = fmaf(gf, c[ci], gi * gg);
                    c[ci] = cm;
                    hv[ul] = go * tanha(cm);
                }
                if (!last) {
                    uint32_t a = (uint32_t)(rf * 3072) + hbase + (uint32_t)(rh * 4);
                    sts32(aNXT + a, pack2h(hv[0], hv[1]));
                } else {
                    int r  = rf * 16 + g8 + 8 * rh;
                    int j0 = wn * 8 + 2 * tig;
                    float* hf = reinterpret_cast<float*>(sm + OFF_HF);
                    hf[r * H + j0]     = hv[0];
                    hf[r * H + j0 + 1] = hv[1];
                }
            }
        }

        // ---- commit x(t+1) into the next buffer ----
        if (!last) {
#pragma unroll
            for (int i = 0; i < 4; i++)
                if (i < nxp)
                    sts32(aNXT + xsa[i], pack2h(xp[i].x, xp[i].y));
        }
    }

    // ======================= FC epilogue (fp32 SIMT, 4-way K split) ==========
    __syncthreads();
    float* smf = reinterpret_cast<float*>(sm);
    const float* hf = reinterpret_cast<const float*>(sm + OFF_HF);
    for (int i = tid; i < OUTD * H; i += NT) smf[OFF_WFC / 4 + i] = W_fc[i];
    if (tid < OUTD) smf[OFF_BFC / 4 + tid] = b_fc[tid];
    __syncthreads();
    {
        const int q = tid >> 7, rr = tid & 127;   // quarter q sums k in [q*16, q*16+16)
        float acc[OUTD];
#pragma unroll
        for (int o = 0; o < OUTD; o++) acc[o] = 0.0f;
#pragma unroll
        for (int p = 0; p < 16; p++) {
            int k = q * 16 + p;
            float hvv = hf[rr * H + k];
#pragma unroll
            for (int o = 0; o < OUTD; o++)
                acc[o] = fmaf(hvv, smf[OFF_WFC / 4 + o * H + k], acc[o]);
        }
#pragma unroll
        for (int o = 0; o < OUTD; o++)
            smf[OFF_PART / 4 + (q * 128 + rr) * OUTD + o] = acc[o];
    }
    __syncthreads();
    for (int i = tid; i < MROWS * OUTD; i += NT) {
        int rr = i / OUTD, o = i - rr * OUTD;
        out[(size_t)(b0 + rr) * OUTD + o] =
            smf[OFF_PART / 4 + rr * OUTD + o]
          + smf[OFF_PART / 4 + (128 + rr) * OUTD + o]
          + smf[OFF_PART / 4 + (256 + rr) * OUTD + o]
          + smf[OFF_PART / 4 + (384 + rr) * OUTD + o]
          + smf[OFF_BFC / 4 + o];
    }
}

extern "C" void kernel_launch(void* const* d_in, const int* in_sizes, int n_in,
                              void* d_out, int out_size) {
    const float* x    = (const float*)d_in[0];
    const float* W_ih = (const float*)d_in[1];
    const float* W_hh = (const float*)d_in[2];
    const float* b_ih = (const float*)d_in[3];
    const float* b_hh = (const float*)d_in[4];
    const float* W_fc = (const float*)d_in[5];
    const float* b_fc = (const float*)d_in[6];

    cudaFuncSetAttribute(lstm_mma_kernel,
                         cudaFuncAttributeMaxDynamicSharedMemorySize, SMEM_BYTES);
    lstm_mma_kernel<<<BTOT / MROWS, NT, SMEM_BYTES>>>(
        x, W_ih, W_hh, b_ih, b_hh, W_fc, b_fc, (float*)d_out);
}